// round 1
// baseline (speedup 1.0000x reference)
#include <cuda_runtime.h>
#include <cuda_bf16.h>
#include <cstdint>

// ---------------------------------------------------------------------------
// MADPSNet: per-agent expert-selected MLP chain.
//   Only the selected expert per agent is observable in the output, so we
//   compute 4 per-agent GEMMs instead of all-E expert GEMMs (8x fewer FLOPs
//   than the reference einsum formulation).
//
//   L1: y1 = relu(in  @ Ws1[e_s] + bs1[e_s])   [2048,256]x[256,512]
//   L2: y2 = relu(y1  @ Ws2[e_s] + bs2[e_s])   [2048,512]x[512,256]
//   L3: y3 = relu(y2  @ Wd1[e_d] + bd1[e_d])   [2048,256]x[256,512]
//   L4: out =      y3 @ Wd2[e_d] + bd2[e_d]    [2048,512]x[512,128]
//
// GEMM: 128x128 block tile, BK=16, 256 threads, 8x8 microtile per thread,
// accumulated as 8x4 packed f32x2 via fma.rn.f32x2 (full-rate fp32 on
// Blackwell; scalar 3-reg FFMA is half-rate).
// ---------------------------------------------------------------------------

#define NUM_AGENTS 8
#define BATCH      2048

// Scratch (allocation-free rule: __device__ globals)
__device__ float g_y1[NUM_AGENTS * BATCH * 512];
__device__ float g_y2[NUM_AGENTS * BATCH * 256];
__device__ float g_y3[NUM_AGENTS * BATCH * 512];

typedef unsigned long long u64;

__device__ __forceinline__ u64 pack2(float lo, float hi) {
    u64 r;
    asm("mov.b64 %0, {%1, %2};" : "=l"(r) : "f"(lo), "f"(hi));
    return r;
}
__device__ __forceinline__ u64 fma2(u64 a, u64 b, u64 c) {
    u64 d;
    asm("fma.rn.f32x2 %0, %1, %2, %3;" : "=l"(d) : "l"(a), "l"(b), "l"(c));
    return d;
}
__device__ __forceinline__ float2 unpack2(u64 v) {
    float2 f;
    asm("mov.b64 {%0, %1}, %2;" : "=f"(f.x), "=f"(f.y) : "l"(v));
    return f;
}

// C[ag] = act(In[ag] @ W[sel[ag]] + b[sel[ag]])
// In:  [NUM_AGENTS, BATCH, K]   W: [E, K, N]   b: [E, N]   C: [NUM_AGENTS, BATCH, N]
template <int K, int N, bool RELU>
__global__ void __launch_bounds__(256)
gemm_sel_kernel(const float* __restrict__ In,
                const float* __restrict__ Wall,
                const float* __restrict__ Ball,
                float* __restrict__ Out,
                const int* __restrict__ sel)
{
    const int ag = blockIdx.z;
    int e = sel[ag];
    e = e < 0 ? 0 : (e > 7 ? 7 : e);   // crash insurance on index dtype

    const float* Ap = In   + (size_t)ag * BATCH * K;
    const float* Wp = Wall + (size_t)e  * K * N;
    const float* bp = Ball + (size_t)e  * N;
    float*       Cp = Out  + (size_t)ag * BATCH * N;

    const int bm = blockIdx.y * 128;
    const int bn = blockIdx.x * 128;

    __shared__ float As[16][128];   // [k][m]
    __shared__ float Ws[16][128];   // [k][n]

    const int tid = threadIdx.x;
    const int tx  = tid & 15;       // column group (8 cols each)
    const int ty  = tid >> 4;       // row group    (8 rows each)

    u64 acc[8][4];
#pragma unroll
    for (int i = 0; i < 8; i++)
#pragma unroll
        for (int j = 0; j < 4; j++) acc[i][j] = 0ull;

    for (int k0 = 0; k0 < K; k0 += 16) {
        // --- load A tile (128 rows x 16 k) : 512 float4, 2 per thread, transpose to As[k][m]
#pragma unroll
        for (int l = 0; l < 2; l++) {
            int fid = tid * 2 + l;
            int m   = fid >> 2;
            int ks  = fid & 3;
            float4 v = *(const float4*)(Ap + (size_t)(bm + m) * K + k0 + ks * 4);
            As[ks * 4 + 0][m] = v.x;
            As[ks * 4 + 1][m] = v.y;
            As[ks * 4 + 2][m] = v.z;
            As[ks * 4 + 3][m] = v.w;
        }
        // --- load W tile (16 k x 128 n) : 512 float4, 2 per thread
#pragma unroll
        for (int l = 0; l < 2; l++) {
            int fid = tid * 2 + l;
            int kk  = fid >> 5;
            int ns  = fid & 31;
            *(float4*)&Ws[kk][ns * 4] =
                *(const float4*)(Wp + (size_t)(k0 + kk) * N + bn + ns * 4);
        }
        __syncthreads();

#pragma unroll
        for (int kk = 0; kk < 16; kk++) {
            // b fragment: 8 consecutive floats = 4 packed f32x2 (two LDS.128)
            ulonglong2 w01 = *(const ulonglong2*)&Ws[kk][tx * 8];
            ulonglong2 w23 = *(const ulonglong2*)(&Ws[kk][tx * 8] + 4);
            u64 b2[4] = {w01.x, w01.y, w23.x, w23.y};
            // a fragment: 8 floats (two LDS.128), splat each into both lanes
            float4 a0 = *(const float4*)&As[kk][ty * 8];
            float4 a1 = *(const float4*)(&As[kk][ty * 8] + 4);
            float av[8] = {a0.x, a0.y, a0.z, a0.w, a1.x, a1.y, a1.z, a1.w};
#pragma unroll
            for (int i = 0; i < 8; i++) {
                u64 a2 = pack2(av[i], av[i]);
#pragma unroll
                for (int j = 0; j < 4; j++)
                    acc[i][j] = fma2(a2, b2[j], acc[i][j]);
            }
        }
        __syncthreads();
    }

    // --- epilogue: bias + optional relu, float4 stores
    float bb[8];
#pragma unroll
    for (int j = 0; j < 8; j++) bb[j] = bp[bn + tx * 8 + j];

#pragma unroll
    for (int i = 0; i < 8; i++) {
        float o[8];
#pragma unroll
        for (int j = 0; j < 4; j++) {
            float2 f = unpack2(acc[i][j]);
            o[2 * j]     = f.x + bb[2 * j];
            o[2 * j + 1] = f.y + bb[2 * j + 1];
        }
        if (RELU) {
#pragma unroll
            for (int j = 0; j < 8; j++) o[j] = fmaxf(o[j], 0.0f);
        }
        float* crow = Cp + (size_t)(bm + ty * 8 + i) * N + bn + tx * 8;
        *(float4*)crow       = make_float4(o[0], o[1], o[2], o[3]);
        *((float4*)crow + 1) = make_float4(o[4], o[5], o[6], o[7]);
    }
}

extern "C" void kernel_launch(void* const* d_in, const int* in_sizes, int n_in,
                              void* d_out, int out_size)
{
    // metadata order == setup_inputs dict order:
    // 0 inputs [8,2048,256] f32
    // 1 laac_shallow [1,8] int
    // 2 laac_deep    [1,8] int
    // 3 Ws1 [8,256,512]  4 bs1 [8,512]
    // 5 Ws2 [8,512,256]  6 bs2 [8,256]
    // 7 Wd1 [8,256,512]  8 bd1 [8,512]
    // 9 Wd2 [8,512,128] 10 bd2 [8,128]
    const float* inputs = (const float*)d_in[0];
    const int*   sel_s  = (const int*)d_in[1];
    const int*   sel_d  = (const int*)d_in[2];
    const float* Ws1 = (const float*)d_in[3];
    const float* bs1 = (const float*)d_in[4];
    const float* Ws2 = (const float*)d_in[5];
    const float* bs2 = (const float*)d_in[6];
    const float* Wd1 = (const float*)d_in[7];
    const float* bd1 = (const float*)d_in[8];
    const float* Wd2 = (const float*)d_in[9];
    const float* bd2 = (const float*)d_in[10];
    float* out = (float*)d_out;

    void *p1, *p2, *p3;
    cudaGetSymbolAddress(&p1, g_y1);
    cudaGetSymbolAddress(&p2, g_y2);
    cudaGetSymbolAddress(&p3, g_y3);
    float* y1 = (float*)p1;
    float* y2 = (float*)p2;
    float* y3 = (float*)p3;

    dim3 blk(256);
    // L1: K=256, N=512
    gemm_sel_kernel<256, 512, true><<<dim3(4, 16, 8), blk>>>(inputs, Ws1, bs1, y1, sel_s);
    // L2: K=512, N=256
    gemm_sel_kernel<512, 256, true><<<dim3(2, 16, 8), blk>>>(y1, Ws2, bs2, y2, sel_s);
    // L3: K=256, N=512
    gemm_sel_kernel<256, 512, true><<<dim3(4, 16, 8), blk>>>(y2, Wd1, bd1, y3, sel_d);
    // L4: K=512, N=128, no relu
    gemm_sel_kernel<512, 128, false><<<dim3(1, 16, 8), blk>>>(y3, Wd2, bd2, out, sel_d);
}